// round 9
// baseline (speedup 1.0000x reference)
#include <cuda_runtime.h>

// Stochastic LIF neuron scan — R8.
// Inputs (metadata order): x [B,T,N] f32, noise [B,T,N] f32, unif [B,T,N] f32.
// Output: spikes [B,T,N] f32.
//
// Bit-exact step per (b,n):
//   u = 0.5*u + x_t        (separate mul+add, NO fma)
//   u = u - noise_t
//   q = ((u - 1) + 0.4) / 0.8   (IEEE div; clip elided — unif ∈ [0,1))
//   o = (unif_t < q);  u = o ? 0 : u
//
// R8 change vs R7 (80.4us, DRAM 84.4% @ 4 CTAs/SM): 4 float4 tiles per thread
// (16 elems over n), grid 512 -> ~2 CTAs/SM. Measured monotone trend R4-R7:
// fewer co-resident CTAs + more per-warp loads in flight -> higher DRAM%.
// Unroll-4 over t, default cache ops, block=256 retained.

#define B_DIM 32
#define T_DIM 16
#define N_DIM 65536
#define N4    (N_DIM / 4)     // 16384 float4 per (b,t) row
#define QTR   (N4 / 4)        // 4096: tile stride within a row

__device__ __forceinline__ void lif_lane(float& u, float xv, float nv, float rv,
                                         float& ov)
{
    float un = __fadd_rn(__fmul_rn(0.5f, u), xv);
    un = __fsub_rn(un, nv);
    float v = __fsub_rn(un, 1.0f);
    float q = __fdiv_rn(__fadd_rn(v, 0.4f), 0.8f);
    bool  s = (rv < q);
    ov = s ? 1.0f : 0.0f;
    u  = s ? 0.0f : un;
}

__device__ __forceinline__ void lif_vec4(float4& u, const float4& xv,
                                         const float4& nv, const float4& rv,
                                         float4& ov)
{
    lif_lane(u.x, xv.x, nv.x, rv.x, ov.x);
    lif_lane(u.y, xv.y, nv.y, rv.y, ov.y);
    lif_lane(u.z, xv.z, nv.z, rv.z, ov.z);
    lif_lane(u.w, xv.w, nv.w, rv.w, ov.w);
}

__global__ __launch_bounds__(256)
void neuron_scan_kernel(const float4* __restrict__ x,
                        const float4* __restrict__ noise,
                        const float4* __restrict__ unif,
                        float4* __restrict__ out)
{
    int tid = blockIdx.x * blockDim.x + threadIdx.x;   // 0 .. B*QTR-1 (grid exact)

    int b   = tid >> 12;            // tid / QTR
    int off = tid & (QTR - 1);      // tid % QTR

    // four float4 tiles per thread: columns off + k*QTR of each row
    int i0 = b * (T_DIM * N4) + off;
    int i1 = i0 + QTR;
    int i2 = i0 + 2 * QTR;
    int i3 = i0 + 3 * QTR;

    float4 ua = make_float4(0.f, 0.f, 0.f, 0.f);
    float4 ub = make_float4(0.f, 0.f, 0.f, 0.f);
    float4 uc = make_float4(0.f, 0.f, 0.f, 0.f);
    float4 ud = make_float4(0.f, 0.f, 0.f, 0.f);

    #pragma unroll 4
    for (int t = 0; t < T_DIM; ++t) {
        float4 xa = x[i0],     xb = x[i1],     xc = x[i2],     xd = x[i3];
        float4 na = noise[i0], nb = noise[i1], nc = noise[i2], nd = noise[i3];
        float4 ra = unif[i0],  rb = unif[i1],  rc = unif[i2],  rd = unif[i3];

        float4 oa, ob, oc, od;
        lif_vec4(ua, xa, na, ra, oa);
        lif_vec4(ub, xb, nb, rb, ob);
        lif_vec4(uc, xc, nc, rc, oc);
        lif_vec4(ud, xd, nd, rd, od);

        out[i0] = oa;
        out[i1] = ob;
        out[i2] = oc;
        out[i3] = od;

        i0 += N4; i1 += N4; i2 += N4; i3 += N4;
    }
}

extern "C" void kernel_launch(void* const* d_in, const int* in_sizes, int n_in,
                              void* d_out, int out_size)
{
    const float4* x     = (const float4*)d_in[0];
    const float4* noise = (const float4*)d_in[1];
    const float4* unif  = (const float4*)d_in[2];
    float4* out         = (float4*)d_out;

    const int total_threads = B_DIM * QTR;         // 131072
    const int block = 256;
    const int grid  = total_threads / block;       // 512, exact

    neuron_scan_kernel<<<grid, block>>>(x, noise, unif, out);
}

// round 10
// speedup vs baseline: 1.0294x; 1.0294x over previous
#include <cuda_runtime.h>

// Stochastic LIF neuron scan — R9.
// Inputs (metadata order): x [B,T,N] f32, noise [B,T,N] f32, unif [B,T,N] f32.
// Output: spikes [B,T,N] f32.
//
// Bit-exact step per (b,n):
//   u = 0.5*u + x_t        (separate mul+add, NO fma)
//   u = u - noise_t
//   q = ((u - 1) + 0.4) / 0.8   (IEEE div; clip elided — unif ∈ [0,1))
//   o = (unif_t < q);  u = o ? 0 : u
//
// R9 = R7's per-thread schedule (2 float4 tiles, 63 regs, best measured:
// 80.4us / DRAM 84.4%) with block 256 -> 512. Same 32 warps/SM, half the
// co-resident CTAs (2 vs 4). R8 showed dropping warps to 16 regresses;
// this isolates CTA granularity at constant warp count / per-warp MLP.
// __launch_bounds__(512, 2) pins 2 CTAs/SM (cap 64 regs; natural use 63).

#define B_DIM 32
#define T_DIM 16
#define N_DIM 65536
#define N4    (N_DIM / 4)     // 16384 float4 per (b,t) row
#define HALF  (N4 / 2)        // 8192: second tile offset within a row

__device__ __forceinline__ void lif_lane(float& u, float xv, float nv, float rv,
                                         float& ov)
{
    float un = __fadd_rn(__fmul_rn(0.5f, u), xv);
    un = __fsub_rn(un, nv);
    float v = __fsub_rn(un, 1.0f);
    float q = __fdiv_rn(__fadd_rn(v, 0.4f), 0.8f);
    bool  s = (rv < q);
    ov = s ? 1.0f : 0.0f;
    u  = s ? 0.0f : un;
}

__global__ __launch_bounds__(512, 2)
void neuron_scan_kernel(const float4* __restrict__ x,
                        const float4* __restrict__ noise,
                        const float4* __restrict__ unif,
                        float4* __restrict__ out)
{
    int tid = blockIdx.x * blockDim.x + threadIdx.x;   // 0 .. B*HALF-1 (grid exact)

    int b   = tid >> 13;            // tid / HALF
    int off = tid & (HALF - 1);     // tid % HALF

    // two float4 tiles per thread: columns off and off+HALF of each row
    int idxA = b * (T_DIM * N4) + off;
    int idxB = idxA + HALF;

    float a0 = 0.0f, a1 = 0.0f, a2 = 0.0f, a3 = 0.0f;
    float b0 = 0.0f, b1 = 0.0f, b2 = 0.0f, b3 = 0.0f;

    #pragma unroll 4
    for (int t = 0; t < T_DIM; ++t) {
        float4 xa = x[idxA];
        float4 xb = x[idxB];
        float4 na = noise[idxA];
        float4 nb = noise[idxB];
        float4 ra = unif[idxA];
        float4 rb = unif[idxB];

        float4 oa, ob;
        lif_lane(a0, xa.x, na.x, ra.x, oa.x);
        lif_lane(a1, xa.y, na.y, ra.y, oa.y);
        lif_lane(a2, xa.z, na.z, ra.z, oa.z);
        lif_lane(a3, xa.w, na.w, ra.w, oa.w);

        lif_lane(b0, xb.x, nb.x, rb.x, ob.x);
        lif_lane(b1, xb.y, nb.y, rb.y, ob.y);
        lif_lane(b2, xb.z, nb.z, rb.z, ob.z);
        lif_lane(b3, xb.w, nb.w, rb.w, ob.w);

        out[idxA] = oa;
        out[idxB] = ob;

        idxA += N4;
        idxB += N4;
    }
}

extern "C" void kernel_launch(void* const* d_in, const int* in_sizes, int n_in,
                              void* d_out, int out_size)
{
    const float4* x     = (const float4*)d_in[0];
    const float4* noise = (const float4*)d_in[1];
    const float4* unif  = (const float4*)d_in[2];
    float4* out         = (float4*)d_out;

    const int total_threads = B_DIM * HALF;        // 262144
    const int block = 512;
    const int grid  = total_threads / block;       // 512, exact

    neuron_scan_kernel<<<grid, block>>>(x, noise, unif, out);
}